// round 3
// baseline (speedup 1.0000x reference)
#include <cuda_runtime.h>
#include <cstdint>

#define NN      50000
#define EE      800000
#define KDIM    128
#define OUTDIM  64
#define CHUNK   512
#define MAXNB   128   // >= ceil(NN/CHUNK) = 98

typedef unsigned long long u64;

// ---------------- device scratch (allocation-free contract) ----------------
__device__ float g_bufB[NN * KDIM];      // h1 between layers
__device__ int   g_cnt[NN];
__device__ int   g_rowptr[NN + 1];
__device__ int   g_cursor[NN];
__device__ int   g_adj[EE];
__device__ float g_Wc[KDIM * OUTDIM];    // W3@W4
__device__ float g_bc[OUTDIM];           // b3@W4 + b4
__device__ int   g_is64;
__device__ int   g_bsum[MAXNB];
__device__ int   g_boff[MAXNB];
__device__ int   g_done;

// ---------------- packed fp32 helpers (sm_103a FFMA2) ----------------
__device__ __forceinline__ u64 pack2(float lo, float hi) {
    u64 r; asm("mov.b64 %0, {%1, %2};" : "=l"(r) : "f"(lo), "f"(hi)); return r;
}
__device__ __forceinline__ void unpack2(u64 v, float& lo, float& hi) {
    asm("mov.b64 {%0, %1}, %2;" : "=f"(lo), "=f"(hi) : "l"(v));
}
__device__ __forceinline__ void ffma2(u64& d, u64 a, u64 b) {
    asm("fma.rn.f32x2 %0, %1, %2, %3;" : "=l"(d) : "l"(a), "l"(b), "l"(d));
}

// ---------------- init: zero counters + dtype detect ----------------
__global__ void init_kernel(const int* __restrict__ ei, int M) {
    int i = blockIdx.x * blockDim.x + threadIdx.x;
    if (i < M) g_cnt[i] = 0;
    if (i == 0) {
        g_done = 0;
        int allz = 1;
        for (int e = 0; e < 64; e++) {
            if (ei[2 * e + 1] != 0) { allz = 0; break; }
        }
        g_is64 = allz;
    }
}

__global__ void count_kernel(const int* __restrict__ ei, int E) {
    int e = blockIdx.x * blockDim.x + threadIdx.x;
    if (e >= E) return;
    int row = g_is64 ? ei[2 * e] : ei[e];
    atomicAdd(&g_cnt[row], 1);
}

// ---------------- block sums + last-block scan of block sums ----------------
__global__ void bsum_scan_kernel(int M, int NB) {
    __shared__ int sh[256];
    __shared__ int lastflag;
    int b = blockIdx.x, t = threadIdx.x;
    int i0 = b * CHUNK + t, i1 = i0 + 256;
    int s = 0;
    if (i0 < M) s += g_cnt[i0];
    if (i1 < M) s += g_cnt[i1];
    sh[t] = s; __syncthreads();
    for (int d = 128; d > 0; d >>= 1) {
        if (t < d) sh[t] += sh[t + d];
        __syncthreads();
    }
    if (t == 0) {
        g_bsum[b] = sh[0];
        __threadfence();
        lastflag = (atomicAdd(&g_done, 1) == NB - 1);
    }
    __syncthreads();
    if (!lastflag) return;

    // last block: scan the NB (<=128) block sums
    __syncthreads();
    int v = (t < NB) ? g_bsum[t] : 0;
    sh[t] = v; __syncthreads();
    for (int d = 1; d < 128; d <<= 1) {
        int u = (t >= d && t < 128) ? sh[t - d] : 0;
        __syncthreads();
        if (t < 128) sh[t] += u;
        __syncthreads();
    }
    if (t < NB) g_boff[t] = sh[t] - v;
    if (t == 127) g_rowptr[M] = sh[127];
}

__global__ void emit_kernel(int M) {
    __shared__ int sh[256];
    int b = blockIdx.x, t = threadIdx.x;
    int base = g_boff[b];
    int i0 = b * CHUNK + 2 * t, i1 = i0 + 1;
    int v0 = (i0 < M) ? g_cnt[i0] : 0;
    int v1 = (i1 < M) ? g_cnt[i1] : 0;
    int s = v0 + v1;
    sh[t] = s; __syncthreads();
    for (int d = 1; d < 256; d <<= 1) {
        int u = (t >= d) ? sh[t - d] : 0;
        __syncthreads();
        sh[t] += u;
        __syncthreads();
    }
    int ex = base + sh[t] - s;
    if (i0 < M) { g_rowptr[i0] = ex;      g_cursor[i0] = ex; }
    if (i1 < M) { g_rowptr[i1] = ex + v0; g_cursor[i1] = ex + v0; }
}

__global__ void fill_kernel(const int* __restrict__ ei, int E) {
    int e = blockIdx.x * blockDim.x + threadIdx.x;
    if (e >= E) return;
    int row, col;
    if (g_is64) {
        row = ei[2 * e];
        col = ei[2 * E + 2 * e];
    } else {
        row = ei[e];
        col = ei[E + e];
    }
    int pos = atomicAdd(&g_cursor[row], 1);
    g_adj[pos] = col;
}

// ---------------- fused post_mp weight precompute ----------------
__global__ void wc_kernel(const float* __restrict__ W3, const float* __restrict__ b3,
                          const float* __restrict__ W4, const float* __restrict__ b4) {
    int blk = blockIdx.x;
    int c = threadIdx.x;
    if (blk < KDIM) {
        float s = 0.0f;
        for (int m = 0; m < KDIM; m++)
            s += W3[blk * KDIM + m] * W4[m * OUTDIM + c];
        g_Wc[blk * OUTDIM + c] = s;
    } else {
        float s = b4[c];
        for (int m = 0; m < KDIM; m++)
            s += b3[m] * W4[m * OUTDIM + c];
        g_bc[c] = s;
    }
}

// ---------------- fused SpMM + GEMM (+ optional post_mp GEMM) ----------------
// Block = 64-row tile. Phase 1: 8 warps gather-propagate 8 rows each into As.
// Phase 2: FFMA2 GEMM As[64,128] @ Ws[128,128] + bias (+relu).
// If POST: h2 -> As, Wc -> Ws, second GEMM As[64,128] @ Wc[128,64] + bc -> dst.
template <bool POST>
__global__ void __launch_bounds__(256, 2)
fused_layer_kernel(const float* __restrict__ src,
                   const float* __restrict__ W,  const float* __restrict__ bias,
                   const float* __restrict__ Wc, const float* __restrict__ bc,
                   float* __restrict__ dst, int M) {
    constexpr int K  = KDIM;
    constexpr int TM = 64;

    extern __shared__ float sm[];
    float* Ws = sm;              // K*128 = 64KB
    float* As = sm + K * 128;    // TM*K  = 32KB

    int tid  = threadIdx.x;
    int warp = tid >> 5;
    int lane = tid & 31;
    int m0   = blockIdx.x * TM;

    // stage W (128x128)
    for (int i = tid; i < K * 128 / 4; i += 256)
        ((float4*)Ws)[i] = ((const float4*)W)[i];

    // gather-propagate: warp handles rows warp*8 .. warp*8+7
    const float4* s4 = (const float4*)src;
    for (int r = 0; r < 8; r++) {
        int lr  = warp * 8 + r;
        int row = m0 + lr;
        float ax = 0.f, ay = 0.f, az = 0.f, aw = 0.f;
        if (row < M) {
            float4 a = s4[(size_t)row * 32 + lane];   // self loop
            ax = a.x; ay = a.y; az = a.z; aw = a.w;
            int e   = g_rowptr[row];
            int end = g_rowptr[row + 1];
            float inv = 1.0f / (float)(end - e + 1);
            for (; e + 8 <= end; e += 8) {
                float4 v[8];
#pragma unroll
                for (int q = 0; q < 8; q++) {
                    int j = g_adj[e + q];
                    v[q] = s4[(size_t)j * 32 + lane];
                }
#pragma unroll
                for (int q = 0; q < 8; q++) {
                    ax += v[q].x; ay += v[q].y; az += v[q].z; aw += v[q].w;
                }
            }
            for (; e < end; e++) {
                int j = g_adj[e];
                float4 v = s4[(size_t)j * 32 + lane];
                ax += v.x; ay += v.y; az += v.z; aw += v.w;
            }
            ax *= inv; ay *= inv; az *= inv; aw *= inv;
        }
        *(float4*)&As[lr * K + lane * 4] = make_float4(ax, ay, az, aw);
    }
    __syncthreads();

    // GEMM1: thread (rt,ct): rows rt*4.., cols ct*8..  (CT=16, RT=16)
    int ct = tid & 15;
    int rt = tid >> 4;
    int c0 = ct * 8;

    u64 acc[4][4];
#pragma unroll
    for (int r = 0; r < 4; r++)
#pragma unroll
        for (int p = 0; p < 4; p++) acc[r][p] = 0ull;

    const float* arow = As + (rt * 4) * K;

#pragma unroll 4
    for (int k = 0; k < K; k++) {
        ulonglong2 wA = *(const ulonglong2*)&Ws[k * 128 + c0];
        ulonglong2 wB = *(const ulonglong2*)&Ws[k * 128 + c0 + 4];
#pragma unroll
        for (int r = 0; r < 4; r++) {
            float a = arow[r * K + k];
            u64 aa = pack2(a, a);
            ffma2(acc[r][0], aa, wA.x);
            ffma2(acc[r][1], aa, wA.y);
            ffma2(acc[r][2], aa, wB.x);
            ffma2(acc[r][3], aa, wB.y);
        }
    }

    float4 bv0 = *(const float4*)&bias[c0];
    float4 bv1 = *(const float4*)&bias[c0 + 4];

    if (!POST) {
        // write relu(h) to dst (stride 128)
#pragma unroll
        for (int r = 0; r < 4; r++) {
            int gr = m0 + rt * 4 + r;
            if (gr >= M) continue;
            float o[8];
            unpack2(acc[r][0], o[0], o[1]);
            unpack2(acc[r][1], o[2], o[3]);
            unpack2(acc[r][2], o[4], o[5]);
            unpack2(acc[r][3], o[6], o[7]);
            o[0] += bv0.x; o[1] += bv0.y; o[2] += bv0.z; o[3] += bv0.w;
            o[4] += bv1.x; o[5] += bv1.y; o[6] += bv1.z; o[7] += bv1.w;
#pragma unroll
            for (int p = 0; p < 8; p++) o[p] = fmaxf(o[p], 0.f);
            *(float4*)&dst[(size_t)gr * 128 + c0]     = make_float4(o[0], o[1], o[2], o[3]);
            *(float4*)&dst[(size_t)gr * 128 + c0 + 4] = make_float4(o[4], o[5], o[6], o[7]);
        }
        return;
    }

    // POST: h2 = relu(acc + b2) -> As (overwrite); Wc -> Ws (overwrite)
    __syncthreads();   // all reads of As/Ws in GEMM1 complete
#pragma unroll
    for (int r = 0; r < 4; r++) {
        int lr = rt * 4 + r;
        float o[8];
        unpack2(acc[r][0], o[0], o[1]);
        unpack2(acc[r][1], o[2], o[3]);
        unpack2(acc[r][2], o[4], o[5]);
        unpack2(acc[r][3], o[6], o[7]);
        o[0] += bv0.x; o[1] += bv0.y; o[2] += bv0.z; o[3] += bv0.w;
        o[4] += bv1.x; o[5] += bv1.y; o[6] += bv1.z; o[7] += bv1.w;
#pragma unroll
        for (int p = 0; p < 8; p++) o[p] = fmaxf(o[p], 0.f);
        *(float4*)&As[lr * K + c0]     = make_float4(o[0], o[1], o[2], o[3]);
        *(float4*)&As[lr * K + c0 + 4] = make_float4(o[4], o[5], o[6], o[7]);
    }
    // load Wc (128x64 = 32KB) into Ws region
    for (int i = tid; i < K * OUTDIM / 4; i += 256)
        ((float4*)Ws)[i] = ((const float4*)Wc)[i];
    __syncthreads();

    // GEMM2: thread (rt2,ct2): rows rt2*2.., cols ct2*8.. (CT=8, RT=32)
    int ct2 = tid & 7;
    int rt2 = tid >> 3;
    int c2  = ct2 * 8;

    u64 acc2[2][4];
#pragma unroll
    for (int r = 0; r < 2; r++)
#pragma unroll
        for (int p = 0; p < 4; p++) acc2[r][p] = 0ull;

    const float* arow2 = As + (rt2 * 2) * K;

#pragma unroll 4
    for (int k = 0; k < K; k++) {
        ulonglong2 wA = *(const ulonglong2*)&Ws[k * OUTDIM + c2];
        ulonglong2 wB = *(const ulonglong2*)&Ws[k * OUTDIM + c2 + 4];
#pragma unroll
        for (int r = 0; r < 2; r++) {
            float a = arow2[r * K + k];
            u64 aa = pack2(a, a);
            ffma2(acc2[r][0], aa, wA.x);
            ffma2(acc2[r][1], aa, wA.y);
            ffma2(acc2[r][2], aa, wB.x);
            ffma2(acc2[r][3], aa, wB.y);
        }
    }

    float4 cv0 = *(const float4*)&bc[c2];
    float4 cv1 = *(const float4*)&bc[c2 + 4];
#pragma unroll
    for (int r = 0; r < 2; r++) {
        int gr = m0 + rt2 * 2 + r;
        if (gr >= M) continue;
        float o[8];
        unpack2(acc2[r][0], o[0], o[1]);
        unpack2(acc2[r][1], o[2], o[3]);
        unpack2(acc2[r][2], o[4], o[5]);
        unpack2(acc2[r][3], o[6], o[7]);
        o[0] += cv0.x; o[1] += cv0.y; o[2] += cv0.z; o[3] += cv0.w;
        o[4] += cv1.x; o[5] += cv1.y; o[6] += cv1.z; o[7] += cv1.w;
        *(float4*)&dst[(size_t)gr * OUTDIM + c2]     = make_float4(o[0], o[1], o[2], o[3]);
        *(float4*)&dst[(size_t)gr * OUTDIM + c2 + 4] = make_float4(o[4], o[5], o[6], o[7]);
    }
}

// ---------------- host launch ----------------
extern "C" void kernel_launch(void* const* d_in, const int* in_sizes, int n_in,
                              void* d_out, int out_size) {
    const float* x  = (const float*)d_in[0];
    const int*   ei = (const int*)d_in[1];
    const float* W1 = (const float*)d_in[2];
    const float* b1 = (const float*)d_in[3];
    const float* W2 = (const float*)d_in[4];
    const float* b2 = (const float*)d_in[5];
    const float* W3 = (const float*)d_in[6];
    const float* b3 = (const float*)d_in[7];
    const float* W4 = (const float*)d_in[8];
    const float* b4 = (const float*)d_in[9];
    float* out = (float*)d_out;

    int M = in_sizes[0] / KDIM;   // 50000
    int E = in_sizes[1] / 2;      // 800000
    int NB = (M + CHUNK - 1) / CHUNK;

    float *bufB, *Wc, *bc;
    cudaGetSymbolAddress((void**)&bufB, g_bufB);
    cudaGetSymbolAddress((void**)&Wc, g_Wc);
    cudaGetSymbolAddress((void**)&bc, g_bc);

    constexpr int SMEM = (KDIM * 128 + 64 * KDIM) * 4;   // 96KB
    cudaFuncSetAttribute(fused_layer_kernel<false>,
                         cudaFuncAttributeMaxDynamicSharedMemorySize, SMEM);
    cudaFuncSetAttribute(fused_layer_kernel<true>,
                         cudaFuncAttributeMaxDynamicSharedMemorySize, SMEM);

    // ---- CSR build ----
    init_kernel<<<(M + 255) / 256, 256>>>(ei, M);
    count_kernel<<<(E + 511) / 512, 512>>>(ei, E);
    bsum_scan_kernel<<<NB, 256>>>(M, NB);
    emit_kernel<<<NB, 256>>>(M);
    fill_kernel<<<(E + 511) / 512, 512>>>(ei, E);
    wc_kernel<<<KDIM + 1, OUTDIM>>>(W3, b3, W4, b4);

    int blocks = (M + 63) / 64;

    // layer 1: relu(propagate(x) @ W1 + b1) -> bufB
    fused_layer_kernel<false><<<blocks, 256, SMEM>>>(x, W1, b1, nullptr, nullptr, bufB, M);
    // layer 2 + post_mp: (relu(propagate(bufB) @ W2 + b2) @ Wc + bc) -> out
    fused_layer_kernel<true><<<blocks, 256, SMEM>>>(bufB, W2, b2, Wc, bc, out, M);
}

// round 4
// speedup vs baseline: 1.2835x; 1.2835x over previous
#include <cuda_runtime.h>
#include <cstdint>

#define NN      50000
#define EE      800000
#define KDIM    128
#define OUTDIM  64
#define CHUNK   512
#define MAXNB   128   // >= ceil(NN/CHUNK) = 98

typedef unsigned long long u64;

// ---------------- device scratch ----------------
__device__ float g_bufA[NN * KDIM];
__device__ float g_bufB[NN * KDIM];
__device__ int   g_cnt[NN];
__device__ int   g_rowptr[NN + 1];
__device__ int   g_cursor[NN];
__device__ int   g_adj[EE];
__device__ float g_invdeg[NN];
__device__ float g_Wc[KDIM * OUTDIM];
__device__ float g_bc[OUTDIM];
__device__ int   g_is64;
__device__ int   g_bsum[MAXNB];
__device__ int   g_done;

// ---------------- packed fp32 helpers ----------------
__device__ __forceinline__ u64 pack2(float lo, float hi) {
    u64 r; asm("mov.b64 %0, {%1, %2};" : "=l"(r) : "f"(lo), "f"(hi)); return r;
}
__device__ __forceinline__ void unpack2(u64 v, float& lo, float& hi) {
    asm("mov.b64 {%0, %1}, %2;" : "=f"(lo), "=f"(hi) : "l"(v));
}
__device__ __forceinline__ void ffma2(u64& d, u64 a, u64 b) {
    asm("fma.rn.f32x2 %0, %1, %2, %3;" : "=l"(d) : "l"(a), "l"(b), "l"(d));
}

// ---------------- init: zero counters + dtype detect ----------------
__global__ void init_kernel(const int* __restrict__ ei, int M) {
    int i = blockIdx.x * blockDim.x + threadIdx.x;
    if (i < M) g_cnt[i] = 0;
    if (i == 0) {
        g_done = 0;
        int allz = 1;
        for (int e = 0; e < 64; e++) {
            if (ei[2 * e + 1] != 0) { allz = 0; break; }
        }
        g_is64 = allz;
    }
}

// resident-grid spin barrier (grid <= SM count guarantees co-residency)
__device__ __forceinline__ void gridbar(int target) {
    __syncthreads();
    if (threadIdx.x == 0) {
        __threadfence();
        atomicAdd(&g_done, 1);
        while (*(volatile int*)&g_done < target) { }
    }
    __syncthreads();
}

// ---------------- single-kernel CSR build ----------------
// NB blocks (<=128, resident). Phases: count -> bsum -> (scan+emit) -> fill.
__global__ void __launch_bounds__(256, 1)
csr_all_kernel(const int* __restrict__ ei, int E, int M, int NB) {
    __shared__ int sh[256];
    int b = blockIdx.x, t = threadIdx.x;
    int is64 = g_is64;
    int stride = NB * 256;

    // ---- phase 1: count ----
    for (int e = b * 256 + t; e < E; e += stride) {
        int row = is64 ? ei[2 * e] : ei[e];
        atomicAdd(&g_cnt[row], 1);
    }
    gridbar(NB);

    // ---- phase 2: per-chunk block sums ----
    {
        int i0 = b * CHUNK + t, i1 = i0 + 256;
        int s = 0;
        if (i0 < M) s += g_cnt[i0];
        if (i1 < M) s += g_cnt[i1];
        sh[t] = s; __syncthreads();
        for (int d = 128; d > 0; d >>= 1) {
            if (t < d) sh[t] += sh[t + d];
            __syncthreads();
        }
        if (t == 0) g_bsum[b] = sh[0];
    }
    gridbar(2 * NB);

    // ---- phase 3: every block scans all block sums (redundant, cheap) ----
    int boff, total;
    {
        int v = (t < NB) ? g_bsum[t] : 0;
        sh[t] = v; __syncthreads();
        for (int d = 1; d < 128; d <<= 1) {
            int u = (t >= d && t < 128) ? sh[t - d] : 0;
            __syncthreads();
            if (t < 128) sh[t] += u;
            __syncthreads();
        }
        total = sh[127];
        boff = (b > 0) ? sh[b - 1] : 0;
        __syncthreads();
    }

    // ---- phase 3b: emit rowptr/cursor/invdeg for this chunk ----
    {
        int i0 = b * CHUNK + 2 * t, i1 = i0 + 1;
        int v0 = (i0 < M) ? g_cnt[i0] : 0;
        int v1 = (i1 < M) ? g_cnt[i1] : 0;
        int s = v0 + v1;
        sh[t] = s; __syncthreads();
        for (int d = 1; d < 256; d <<= 1) {
            int u = (t >= d) ? sh[t - d] : 0;
            __syncthreads();
            sh[t] += u;
            __syncthreads();
        }
        int ex = boff + sh[t] - s;
        if (i0 < M) {
            g_rowptr[i0] = ex; g_cursor[i0] = ex;
            g_invdeg[i0] = 1.0f / (float)(v0 + 1);
        }
        if (i1 < M) {
            g_rowptr[i1] = ex + v0; g_cursor[i1] = ex + v0;
            g_invdeg[i1] = 1.0f / (float)(v1 + 1);
        }
        if (b == 0 && t == 0) g_rowptr[M] = total;
    }
    gridbar(3 * NB);

    // ---- phase 4: fill adjacency ----
    for (int e = b * 256 + t; e < E; e += stride) {
        int row, col;
        if (is64) {
            row = ei[2 * e];
            col = ei[2 * E + 2 * e];
        } else {
            row = ei[e];
            col = ei[E + e];
        }
        int pos = atomicAdd(&g_cursor[row], 1);
        g_adj[pos] = col;
    }
}

// ---------------- fused post_mp weight precompute ----------------
__global__ void wc_kernel(const float* __restrict__ W3, const float* __restrict__ b3,
                          const float* __restrict__ W4, const float* __restrict__ b4) {
    int blk = blockIdx.x;
    int c = threadIdx.x;
    if (blk < KDIM) {
        float s = 0.0f;
        for (int m = 0; m < KDIM; m++)
            s += W3[blk * KDIM + m] * W4[m * OUTDIM + c];
        g_Wc[blk * OUTDIM + c] = s;
    } else {
        float s = b4[c];
        for (int m = 0; m < KDIM; m++)
            s += b3[m] * W4[m * OUTDIM + c];
        g_bc[c] = s;
    }
}

// ---------------- SpMM: warp per row, gather-only (R2-proven) ----------------
__global__ void spmm_kernel(const float* __restrict__ src,
                            float* __restrict__ dst, int M) {
    int warp = (blockIdx.x * blockDim.x + threadIdx.x) >> 5;
    if (warp >= M) return;
    int lane = threadIdx.x & 31;

    const float4* s4 = (const float4*)src;
    size_t rowbase = (size_t)warp * (KDIM / 4);

    float4 a = s4[rowbase + lane];
    float ax = a.x, ay = a.y, az = a.z, aw = a.w;

    int e   = g_rowptr[warp];
    int end = g_rowptr[warp + 1];

    for (; e + 8 <= end; e += 8) {
        float4 v[8];
#pragma unroll
        for (int q = 0; q < 8; q++) {
            int j = g_adj[e + q];
            v[q] = s4[(size_t)j * (KDIM / 4) + lane];
        }
#pragma unroll
        for (int q = 0; q < 8; q++) {
            ax += v[q].x; ay += v[q].y; az += v[q].z; aw += v[q].w;
        }
    }
    for (; e < end; e++) {
        int j = g_adj[e];
        float4 v = s4[(size_t)j * (KDIM / 4) + lane];
        ax += v.x; ay += v.y; az += v.z; aw += v.w;
    }

    float inv = g_invdeg[warp];
    float4 o;
    o.x = ax * inv; o.y = ay * inv; o.z = az * inv; o.w = aw * inv;
    ((float4*)dst)[rowbase + lane] = o;
}

// ---------------- GEMM v3: conflict-free FFMA2, k-vectorized A ----------------
// C[M,NOUT] = A[M,128] @ W[128,NOUT] + bias.
// Thread owns 4 rows x 8 cols, cols split as [ct*4, ct*4+3] and [NOUT/2+ct*4, ...]
// so every 8-lane LDS phase reads 128B contiguous (no bank conflicts).
template <int NOUT, bool RELU>
__global__ void __launch_bounds__(256, 2)
gemm_kernel(const float* __restrict__ A, const float* __restrict__ W,
            const float* __restrict__ bias, float* __restrict__ C, int M) {
    constexpr int K   = KDIM;
    constexpr int CT  = NOUT / 8;      // 16 (NOUT=128) or 8 (NOUT=64)
    constexpr int RT  = 256 / CT;      // 16 or 32
    constexpr int RPT = 4;
    constexpr int TM  = RT * RPT;      // 64 or 128
    constexpr int HALF = NOUT / 2;

    extern __shared__ float sm[];
    float* Ws = sm;                    // K * NOUT
    float* As = sm + K * NOUT;         // TM * K

    int tid = threadIdx.x;
    int m0  = blockIdx.x * TM;

    for (int i = tid; i < K * NOUT / 4; i += 256)
        ((float4*)Ws)[i] = ((const float4*)W)[i];
    for (int i = tid; i < TM * K / 4; i += 256) {
        int r  = i >> 5;
        int gr = m0 + r;
        ((float4*)As)[i] = (gr < M) ? ((const float4*)A)[(size_t)gr * 32 + (i & 31)]
                                    : make_float4(0.f, 0.f, 0.f, 0.f);
    }
    __syncthreads();

    int ct = tid % CT;
    int rt = tid / CT;
    int cL = ct * 4;          // low-half cols
    int cH = HALF + ct * 4;   // high-half cols

    u64 acc[RPT][4];          // [row][loPair0, loPair1, hiPair0, hiPair1]
#pragma unroll
    for (int r = 0; r < RPT; r++)
#pragma unroll
        for (int p = 0; p < 4; p++) acc[r][p] = 0ull;

    const float* arow = As + (rt * RPT) * K;

#pragma unroll 2
    for (int k4 = 0; k4 < K / 4; k4++) {
        int kb = k4 * 4;
        float4 av[RPT];
#pragma unroll
        for (int r = 0; r < RPT; r++)
            av[r] = *(const float4*)&arow[r * K + kb];

#pragma unroll
        for (int kk = 0; kk < 4; kk++) {
            ulonglong2 wlo = *(const ulonglong2*)&Ws[(kb + kk) * NOUT + cL];
            ulonglong2 whi = *(const ulonglong2*)&Ws[(kb + kk) * NOUT + cH];
#pragma unroll
            for (int r = 0; r < RPT; r++) {
                float a = (kk == 0) ? av[r].x : (kk == 1) ? av[r].y
                        : (kk == 2) ? av[r].z : av[r].w;
                u64 aa = pack2(a, a);
                ffma2(acc[r][0], aa, wlo.x);
                ffma2(acc[r][1], aa, wlo.y);
                ffma2(acc[r][2], aa, whi.x);
                ffma2(acc[r][3], aa, whi.y);
            }
        }
    }

    float4 bvL = *(const float4*)&bias[cL];
    float4 bvH = *(const float4*)&bias[cH];

#pragma unroll
    for (int r = 0; r < RPT; r++) {
        int gr = m0 + rt * RPT + r;
        if (gr >= M) continue;
        float o[8];
        unpack2(acc[r][0], o[0], o[1]);
        unpack2(acc[r][1], o[2], o[3]);
        unpack2(acc[r][2], o[4], o[5]);
        unpack2(acc[r][3], o[6], o[7]);
        o[0] += bvL.x; o[1] += bvL.y; o[2] += bvL.z; o[3] += bvL.w;
        o[4] += bvH.x; o[5] += bvH.y; o[6] += bvH.z; o[7] += bvH.w;
        if (RELU) {
#pragma unroll
            for (int p = 0; p < 8; p++) o[p] = fmaxf(o[p], 0.f);
        }
        *(float4*)&C[(size_t)gr * NOUT + cL] = make_float4(o[0], o[1], o[2], o[3]);
        *(float4*)&C[(size_t)gr * NOUT + cH] = make_float4(o[4], o[5], o[6], o[7]);
    }
}

// ---------------- host launch ----------------
extern "C" void kernel_launch(void* const* d_in, const int* in_sizes, int n_in,
                              void* d_out, int out_size) {
    const float* x  = (const float*)d_in[0];
    const int*   ei = (const int*)d_in[1];
    const float* W1 = (const float*)d_in[2];
    const float* b1 = (const float*)d_in[3];
    const float* W2 = (const float*)d_in[4];
    const float* b2 = (const float*)d_in[5];
    const float* W3 = (const float*)d_in[6];
    const float* b3 = (const float*)d_in[7];
    const float* W4 = (const float*)d_in[8];
    const float* b4 = (const float*)d_in[9];
    float* out = (float*)d_out;

    int M = in_sizes[0] / KDIM;   // 50000
    int E = in_sizes[1] / 2;      // 800000
    int NB = (M + CHUNK - 1) / CHUNK;   // 98

    float *bufA, *bufB, *Wc, *bc;
    cudaGetSymbolAddress((void**)&bufA, g_bufA);
    cudaGetSymbolAddress((void**)&bufB, g_bufB);
    cudaGetSymbolAddress((void**)&Wc, g_Wc);
    cudaGetSymbolAddress((void**)&bc, g_bc);

    constexpr int SMEM128 = (KDIM * 128 + 64 * KDIM) * 4;     // 96KB
    constexpr int SMEM64  = (KDIM * OUTDIM + 128 * KDIM) * 4; // 96KB
    cudaFuncSetAttribute(gemm_kernel<128, true>,
                         cudaFuncAttributeMaxDynamicSharedMemorySize, SMEM128);
    cudaFuncSetAttribute(gemm_kernel<64, false>,
                         cudaFuncAttributeMaxDynamicSharedMemorySize, SMEM64);

    // launch order puts spmm at #4 for ncu capture
    init_kernel<<<(M + 255) / 256, 256>>>(ei, M);
    csr_all_kernel<<<NB, 256>>>(ei, E, M, NB);
    wc_kernel<<<KDIM + 1, OUTDIM>>>(W3, b3, W4, b4);

    int spmm_blocks = (M * 32 + 255) / 256;

    spmm_kernel<<<spmm_blocks, 256>>>(x, bufA, M);
    gemm_kernel<128, true><<<(M + 63) / 64, 256, SMEM128>>>(bufA, W1, b1, bufB, M);

    spmm_kernel<<<spmm_blocks, 256>>>(bufB, bufA, M);
    gemm_kernel<128, true><<<(M + 63) / 64, 256, SMEM128>>>(bufA, W2, b2, bufB, M);

    gemm_kernel<64, false><<<(M + 127) / 128, 256, SMEM64>>>(bufB, Wc, bc, out, M);
}

// round 5
// speedup vs baseline: 1.2925x; 1.0070x over previous
#include <cuda_runtime.h>
#include <cstdint>

#define NN      50000
#define EE      800000
#define KDIM    128
#define OUTDIM  64
#define CHUNK   512
#define MAXNB   128   // >= ceil(NN/CHUNK) = 98

typedef unsigned long long u64;

// ---------------- device scratch ----------------
__device__ float g_bufA[NN * KDIM];
__device__ float g_bufB[NN * KDIM];
__device__ int   g_cnt[NN];
__device__ int   g_rowptr[NN + 1];
__device__ int   g_cursor[NN];
__device__ int   g_adj[EE];
__device__ float g_invdeg[NN];
__device__ float g_Wc[KDIM * OUTDIM];
__device__ float g_bc[OUTDIM];
__device__ int   g_is64;
__device__ int   g_bsum[MAXNB];
__device__ int   g_done;

// ---------------- packed fp32 helpers ----------------
__device__ __forceinline__ u64 pack2(float lo, float hi) {
    u64 r; asm("mov.b64 %0, {%1, %2};" : "=l"(r) : "f"(lo), "f"(hi)); return r;
}
__device__ __forceinline__ void unpack2(u64 v, float& lo, float& hi) {
    asm("mov.b64 {%0, %1}, %2;" : "=f"(lo), "=f"(hi) : "l"(v));
}
__device__ __forceinline__ void ffma2(u64& d, u64 a, u64 b) {
    asm("fma.rn.f32x2 %0, %1, %2, %3;" : "=l"(d) : "l"(a), "l"(b), "l"(d));
}

// ---------------- init: zero counters + dtype detect ----------------
__global__ void init_kernel(const int* __restrict__ ei, int M) {
    int i = blockIdx.x * blockDim.x + threadIdx.x;
    if (i < M) g_cnt[i] = 0;
    if (i == 0) {
        g_done = 0;
        int allz = 1;
        for (int e = 0; e < 64; e++) {
            if (ei[2 * e + 1] != 0) { allz = 0; break; }
        }
        g_is64 = allz;
    }
}

// ---------------- count: full grid ----------------
__global__ void count_kernel(const int* __restrict__ ei, int E) {
    int e = blockIdx.x * blockDim.x + threadIdx.x;
    if (e >= E) return;
    int row = g_is64 ? ei[2 * e] : ei[e];
    atomicAdd(&g_cnt[row], 1);
}

// ---------------- scan: 98 resident blocks, bsum -> bar -> scan+emit ----------------
__global__ void __launch_bounds__(256, 1)
scan_kernel(int M, int NB) {
    __shared__ int sh[256];
    int b = blockIdx.x, t = threadIdx.x;

    // per-chunk block sum
    int i0 = b * CHUNK + t, i1 = i0 + 256;
    int s = 0;
    if (i0 < M) s += g_cnt[i0];
    if (i1 < M) s += g_cnt[i1];
    sh[t] = s; __syncthreads();
    for (int d = 128; d > 0; d >>= 1) {
        if (t < d) sh[t] += sh[t + d];
        __syncthreads();
    }
    if (t == 0) {
        g_bsum[b] = sh[0];
        __threadfence();
        atomicAdd(&g_done, 1);
        while (*(volatile int*)&g_done < NB) { }
    }
    __syncthreads();

    // every block scans all block sums (redundant, cheap)
    int v = (t < NB) ? g_bsum[t] : 0;
    sh[t] = v; __syncthreads();
    for (int d = 1; d < 128; d <<= 1) {
        int u = (t >= d && t < 128) ? sh[t - d] : 0;
        __syncthreads();
        if (t < 128) sh[t] += u;
        __syncthreads();
    }
    int total = sh[127];
    int boff  = (b > 0) ? sh[b - 1] : 0;
    __syncthreads();

    // emit rowptr/cursor/invdeg for this chunk
    int j0 = b * CHUNK + 2 * t, j1 = j0 + 1;
    int v0 = (j0 < M) ? g_cnt[j0] : 0;
    int v1 = (j1 < M) ? g_cnt[j1] : 0;
    int ss = v0 + v1;
    sh[t] = ss; __syncthreads();
    for (int d = 1; d < 256; d <<= 1) {
        int u = (t >= d) ? sh[t - d] : 0;
        __syncthreads();
        sh[t] += u;
        __syncthreads();
    }
    int ex = boff + sh[t] - ss;
    if (j0 < M) {
        g_rowptr[j0] = ex; g_cursor[j0] = ex;
        g_invdeg[j0] = 1.0f / (float)(v0 + 1);
    }
    if (j1 < M) {
        g_rowptr[j1] = ex + v0; g_cursor[j1] = ex + v0;
        g_invdeg[j1] = 1.0f / (float)(v1 + 1);
    }
    if (b == 0 && t == 0) g_rowptr[M] = total;
}

// ---------------- fill: full grid ----------------
__global__ void fill_kernel(const int* __restrict__ ei, int E) {
    int e = blockIdx.x * blockDim.x + threadIdx.x;
    if (e >= E) return;
    int row, col;
    if (g_is64) {
        row = ei[2 * e];
        col = ei[2 * E + 2 * e];
    } else {
        row = ei[e];
        col = ei[E + e];
    }
    int pos = atomicAdd(&g_cursor[row], 1);
    g_adj[pos] = col;
}

// ---------------- fused post_mp weight precompute ----------------
__global__ void wc_kernel(const float* __restrict__ W3, const float* __restrict__ b3,
                          const float* __restrict__ W4, const float* __restrict__ b4) {
    int blk = blockIdx.x;
    int c = threadIdx.x;
    if (blk < KDIM) {
        float s = 0.0f;
        for (int m = 0; m < KDIM; m++)
            s += W3[blk * KDIM + m] * W4[m * OUTDIM + c];
        g_Wc[blk * OUTDIM + c] = s;
    } else {
        float s = b4[c];
        for (int m = 0; m < KDIM; m++)
            s += b3[m] * W4[m * OUTDIM + c];
        g_bc[c] = s;
    }
}

// ---------------- SpMM: warp per row, gather-only (proven) ----------------
__global__ void spmm_kernel(const float* __restrict__ src,
                            float* __restrict__ dst, int M) {
    int warp = (blockIdx.x * blockDim.x + threadIdx.x) >> 5;
    if (warp >= M) return;
    int lane = threadIdx.x & 31;

    const float4* s4 = (const float4*)src;
    size_t rowbase = (size_t)warp * (KDIM / 4);

    float4 a = s4[rowbase + lane];
    float ax = a.x, ay = a.y, az = a.z, aw = a.w;

    int e   = g_rowptr[warp];
    int end = g_rowptr[warp + 1];

    for (; e + 8 <= end; e += 8) {
        float4 v[8];
#pragma unroll
        for (int q = 0; q < 8; q++) {
            int j = g_adj[e + q];
            v[q] = s4[(size_t)j * (KDIM / 4) + lane];
        }
#pragma unroll
        for (int q = 0; q < 8; q++) {
            ax += v[q].x; ay += v[q].y; az += v[q].z; aw += v[q].w;
        }
    }
    for (; e < end; e++) {
        int j = g_adj[e];
        float4 v = s4[(size_t)j * (KDIM / 4) + lane];
        ax += v.x; ay += v.y; az += v.z; aw += v.w;
    }

    float inv = g_invdeg[warp];
    float4 o;
    o.x = ax * inv; o.y = ay * inv; o.z = az * inv; o.w = aw * inv;
    ((float4*)dst)[rowbase + lane] = o;
}

// ---------------- GEMM v4: RPT=8 (LDS/FFMA2 balanced), TM=128, 1 CTA/SM ----------------
// C = relu(A[M,128] @ W[128,128] + bias); if POST, additionally
// out = (that) @ Wc[128,64] + bc written to dst (stride 64), else dst stride 128.
template <bool POST>
__global__ void __launch_bounds__(256, 1)
gemm_kernel(const float* __restrict__ A, const float* __restrict__ W,
            const float* __restrict__ bias,
            const float* __restrict__ Wc, const float* __restrict__ bc,
            float* __restrict__ dst, int M) {
    constexpr int K   = KDIM;
    constexpr int CT  = 16;          // 8 cols per thread (two float4 halves)
    constexpr int RPT = 8;
    constexpr int TM  = 128;

    extern __shared__ float sm[];
    float* Ws = sm;                  // 128*128 = 64KB
    float* As = sm + K * 128;        // 128*128 = 64KB

    int tid = threadIdx.x;
    int m0  = blockIdx.x * TM;

    for (int i = tid; i < K * 128 / 4; i += 256)
        ((float4*)Ws)[i] = ((const float4*)W)[i];
    for (int i = tid; i < TM * K / 4; i += 256) {
        int r  = i >> 5;
        int gr = m0 + r;
        ((float4*)As)[i] = (gr < M) ? ((const float4*)A)[(size_t)gr * 32 + (i & 31)]
                                    : make_float4(0.f, 0.f, 0.f, 0.f);
    }
    __syncthreads();

    int ct = tid % CT;
    int rt = tid / CT;               // 0..15
    int cL = ct * 4;                 // cols [cL, cL+3]
    int cH = 64 + ct * 4;            // cols [cH, cH+3]

    u64 acc[RPT][4];
#pragma unroll
    for (int r = 0; r < RPT; r++)
#pragma unroll
        for (int p = 0; p < 4; p++) acc[r][p] = 0ull;

    const float* arow = As + (rt * RPT) * K;

#pragma unroll 2
    for (int k4 = 0; k4 < K / 4; k4++) {
        int kb = k4 * 4;
        float4 av[RPT];
#pragma unroll
        for (int r = 0; r < RPT; r++)
            av[r] = *(const float4*)&arow[r * K + kb];

#pragma unroll
        for (int kk = 0; kk < 4; kk++) {
            ulonglong2 wlo = *(const ulonglong2*)&Ws[(kb + kk) * 128 + cL];
            ulonglong2 whi = *(const ulonglong2*)&Ws[(kb + kk) * 128 + cH];
#pragma unroll
            for (int r = 0; r < RPT; r++) {
                float a = (kk == 0) ? av[r].x : (kk == 1) ? av[r].y
                        : (kk == 2) ? av[r].z : av[r].w;
                u64 aa = pack2(a, a);
                ffma2(acc[r][0], aa, wlo.x);
                ffma2(acc[r][1], aa, wlo.y);
                ffma2(acc[r][2], aa, whi.x);
                ffma2(acc[r][3], aa, whi.y);
            }
        }
    }

    float4 bvL = *(const float4*)&bias[cL];
    float4 bvH = *(const float4*)&bias[cH];

    if (!POST) {
#pragma unroll
        for (int r = 0; r < RPT; r++) {
            int gr = m0 + rt * RPT + r;
            if (gr >= M) continue;
            float o[8];
            unpack2(acc[r][0], o[0], o[1]);
            unpack2(acc[r][1], o[2], o[3]);
            unpack2(acc[r][2], o[4], o[5]);
            unpack2(acc[r][3], o[6], o[7]);
            o[0] += bvL.x; o[1] += bvL.y; o[2] += bvL.z; o[3] += bvL.w;
            o[4] += bvH.x; o[5] += bvH.y; o[6] += bvH.z; o[7] += bvH.w;
#pragma unroll
            for (int p = 0; p < 8; p++) o[p] = fmaxf(o[p], 0.f);
            *(float4*)&dst[(size_t)gr * 128 + cL] = make_float4(o[0], o[1], o[2], o[3]);
            *(float4*)&dst[(size_t)gr * 128 + cH] = make_float4(o[4], o[5], o[6], o[7]);
        }
        return;
    }

    // POST: h2 = relu(.) -> As; Wc -> Ws; GEMM2 -> dst (stride 64)
    __syncthreads();   // all GEMM1 reads of As/Ws complete
#pragma unroll
    for (int r = 0; r < RPT; r++) {
        int lr = rt * RPT + r;
        float o[8];
        unpack2(acc[r][0], o[0], o[1]);
        unpack2(acc[r][1], o[2], o[3]);
        unpack2(acc[r][2], o[4], o[5]);
        unpack2(acc[r][3], o[6], o[7]);
        o[0] += bvL.x; o[1] += bvL.y; o[2] += bvL.z; o[3] += bvL.w;
        o[4] += bvH.x; o[5] += bvH.y; o[6] += bvH.z; o[7] += bvH.w;
#pragma unroll
        for (int p = 0; p < 8; p++) o[p] = fmaxf(o[p], 0.f);
        *(float4*)&As[lr * K + cL] = make_float4(o[0], o[1], o[2], o[3]);
        *(float4*)&As[lr * K + cH] = make_float4(o[4], o[5], o[6], o[7]);
    }
    for (int i = tid; i < K * OUTDIM / 4; i += 256)
        ((float4*)Ws)[i] = ((const float4*)Wc)[i];
    __syncthreads();

    // GEMM2: CT2=8 (8 cols/thread over 64), RT2=32, RPT2=4 -> 128 rows
    int ct2 = tid % 8;
    int rt2 = tid / 8;
    int c2L = ct2 * 4;
    int c2H = 32 + ct2 * 4;

    u64 acc2[4][4];
#pragma unroll
    for (int r = 0; r < 4; r++)
#pragma unroll
        for (int p = 0; p < 4; p++) acc2[r][p] = 0ull;

    const float* arow2 = As + (rt2 * 4) * K;

#pragma unroll 2
    for (int k4 = 0; k4 < K / 4; k4++) {
        int kb = k4 * 4;
        float4 av[4];
#pragma unroll
        for (int r = 0; r < 4; r++)
            av[r] = *(const float4*)&arow2[r * K + kb];
#pragma unroll
        for (int kk = 0; kk < 4; kk++) {
            ulonglong2 wlo = *(const ulonglong2*)&Ws[(kb + kk) * OUTDIM + c2L];
            ulonglong2 whi = *(const ulonglong2*)&Ws[(kb + kk) * OUTDIM + c2H];
#pragma unroll
            for (int r = 0; r < 4; r++) {
                float a = (kk == 0) ? av[r].x : (kk == 1) ? av[r].y
                        : (kk == 2) ? av[r].z : av[r].w;
                u64 aa = pack2(a, a);
                ffma2(acc2[r][0], aa, wlo.x);
                ffma2(acc2[r][1], aa, wlo.y);
                ffma2(acc2[r][2], aa, whi.x);
                ffma2(acc2[r][3], aa, whi.y);
            }
        }
    }

    float4 cvL = *(const float4*)&bc[c2L];
    float4 cvH = *(const float4*)&bc[c2H];
#pragma unroll
    for (int r = 0; r < 4; r++) {
        int gr = m0 + rt2 * 4 + r;
        if (gr >= M) continue;
        float o[8];
        unpack2(acc2[r][0], o[0], o[1]);
        unpack2(acc2[r][1], o[2], o[3]);
        unpack2(acc2[r][2], o[4], o[5]);
        unpack2(acc2[r][3], o[6], o[7]);
        o[0] += cvL.x; o[1] += cvL.y; o[2] += cvL.z; o[3] += cvL.w;
        o[4] += cvH.x; o[5] += cvH.y; o[6] += cvH.z; o[7] += cvH.w;
        *(float4*)&dst[(size_t)gr * OUTDIM + c2L] = make_float4(o[0], o[1], o[2], o[3]);
        *(float4*)&dst[(size_t)gr * OUTDIM + c2H] = make_float4(o[4], o[5], o[6], o[7]);
    }
}

// ---------------- host launch ----------------
extern "C" void kernel_launch(void* const* d_in, const int* in_sizes, int n_in,
                              void* d_out, int out_size) {
    const float* x  = (const float*)d_in[0];
    const int*   ei = (const int*)d_in[1];
    const float* W1 = (const float*)d_in[2];
    const float* b1 = (const float*)d_in[3];
    const float* W2 = (const float*)d_in[4];
    const float* b2 = (const float*)d_in[5];
    const float* W3 = (const float*)d_in[6];
    const float* b3 = (const float*)d_in[7];
    const float* W4 = (const float*)d_in[8];
    const float* b4 = (const float*)d_in[9];
    float* out = (float*)d_out;

    int M = in_sizes[0] / KDIM;         // 50000
    int E = in_sizes[1] / 2;            // 800000
    int NB = (M + CHUNK - 1) / CHUNK;   // 98

    float *bufA, *bufB, *Wc, *bc;
    cudaGetSymbolAddress((void**)&bufA, g_bufA);
    cudaGetSymbolAddress((void**)&bufB, g_bufB);
    cudaGetSymbolAddress((void**)&Wc, g_Wc);
    cudaGetSymbolAddress((void**)&bc, g_bc);

    constexpr int SMEM = (KDIM * 128 + 128 * KDIM) * 4;   // 128KB
    cudaFuncSetAttribute(gemm_kernel<false>,
                         cudaFuncAttributeMaxDynamicSharedMemorySize, SMEM);
    cudaFuncSetAttribute(gemm_kernel<true>,
                         cudaFuncAttributeMaxDynamicSharedMemorySize, SMEM);

    // ---- CSR build (count/fill full grid; scan on 98 resident blocks) ----
    init_kernel<<<(M + 255) / 256, 256>>>(ei, M);
    count_kernel<<<(E + 511) / 512, 512>>>(ei, E);
    scan_kernel<<<NB, 256>>>(M, NB);
    fill_kernel<<<(E + 511) / 512, 512>>>(ei, E);
    wc_kernel<<<KDIM + 1, OUTDIM>>>(W3, b3, W4, b4);

    int spmm_blocks = (M * 32 + 255) / 256;
    int gemm_blocks = (M + 127) / 128;

    // layer 1
    spmm_kernel<<<spmm_blocks, 256>>>(x, bufA, M);
    gemm_kernel<false><<<gemm_blocks, 256, SMEM>>>(bufA, W1, b1, nullptr, nullptr, bufB, M);

    // layer 2 + fused post_mp
    spmm_kernel<<<spmm_blocks, 256>>>(bufB, bufA, M);
    gemm_kernel<true><<<gemm_blocks, 256, SMEM>>>(bufA, W2, b2, Wc, bc, out, M);
}

// round 6
// speedup vs baseline: 1.4413x; 1.1151x over previous
#include <cuda_runtime.h>
#include <cstdint>

#define NN      50000
#define EE      800000
#define KDIM    128
#define OUTDIM  64
#define CHUNK   512
#define MAXNB   128   // >= ceil(NN/CHUNK) = 98

typedef unsigned long long u64;

// ---------------- device scratch ----------------
__device__ float g_bufA[NN * KDIM];
__device__ float g_bufB[NN * KDIM];
__device__ int   g_cnt[NN];
__device__ int   g_rowptr[NN + 1];
__device__ int   g_cursor[NN];
__device__ int   g_adj[EE];
__device__ float g_invdeg[NN];
__device__ float g_Wc[KDIM * OUTDIM];
__device__ float g_bc[OUTDIM];
__device__ int   g_is64;
__device__ int   g_bsum[MAXNB];
__device__ int   g_done;

// ---------------- packed fp32 helpers ----------------
__device__ __forceinline__ u64 pack2(float lo, float hi) {
    u64 r; asm("mov.b64 %0, {%1, %2};" : "=l"(r) : "f"(lo), "f"(hi)); return r;
}
__device__ __forceinline__ void unpack2(u64 v, float& lo, float& hi) {
    asm("mov.b64 {%0, %1}, %2;" : "=f"(lo), "=f"(hi) : "l"(v));
}
__device__ __forceinline__ void ffma2(u64& d, u64 a, u64 b) {
    asm("fma.rn.f32x2 %0, %1, %2, %3;" : "=l"(d) : "l"(a), "l"(b), "l"(d));
}

// ---------------- merged init (zero cnt + detect) and wc precompute ----------------
// blocks [0, ZB): zero g_cnt, block 0 thread 0 detects dtype + resets g_done
// blocks [ZB, ZB+WB): compute g_Wc = W3@W4 and g_bc = b3@W4 + b4
__global__ void initwc_kernel(const int* __restrict__ ei, int M, int ZB,
                              const float* __restrict__ W3, const float* __restrict__ b3,
                              const float* __restrict__ W4, const float* __restrict__ b4) {
    int b = blockIdx.x, t = threadIdx.x;
    if (b < ZB) {
        int i = b * 256 + t;
        if (i < M) g_cnt[i] = 0;
        if (b == 0 && t == 0) {
            g_done = 0;
            int allz = 1;
            for (int e = 0; e < 64; e++) {
                if (ei[2 * e + 1] != 0) { allz = 0; break; }
            }
            g_is64 = allz;
        }
        return;
    }
    int idx = (b - ZB) * 256 + t;           // [0, 129*64)
    if (idx >= (KDIM + 1) * OUTDIM) return;
    int row = idx / OUTDIM;
    int col = idx % OUTDIM;
    if (row < KDIM) {
        float s = 0.0f;
        for (int m = 0; m < KDIM; m++)
            s += W3[row * KDIM + m] * W4[m * OUTDIM + col];
        g_Wc[row * OUTDIM + col] = s;
    } else {
        float s = b4[col];
        for (int m = 0; m < KDIM; m++)
            s += b3[m] * W4[m * OUTDIM + col];
        g_bc[col] = s;
    }
}

// ---------------- count: full grid ----------------
__global__ void count_kernel(const int* __restrict__ ei, int E) {
    int e = blockIdx.x * blockDim.x + threadIdx.x;
    if (e >= E) return;
    int row = g_is64 ? ei[2 * e] : ei[e];
    atomicAdd(&g_cnt[row], 1);
}

// ---------------- scan: 98 resident blocks ----------------
__global__ void __launch_bounds__(256, 1)
scan_kernel(int M, int NB) {
    __shared__ int sh[256];
    int b = blockIdx.x, t = threadIdx.x;

    int i0 = b * CHUNK + t, i1 = i0 + 256;
    int s = 0;
    if (i0 < M) s += g_cnt[i0];
    if (i1 < M) s += g_cnt[i1];
    sh[t] = s; __syncthreads();
    for (int d = 128; d > 0; d >>= 1) {
        if (t < d) sh[t] += sh[t + d];
        __syncthreads();
    }
    if (t == 0) {
        g_bsum[b] = sh[0];
        __threadfence();
        atomicAdd(&g_done, 1);
        while (*(volatile int*)&g_done < NB) { }
    }
    __syncthreads();

    int v = (t < NB) ? g_bsum[t] : 0;
    sh[t] = v; __syncthreads();
    for (int d = 1; d < 128; d <<= 1) {
        int u = (t >= d && t < 128) ? sh[t - d] : 0;
        __syncthreads();
        if (t < 128) sh[t] += u;
        __syncthreads();
    }
    int total = sh[127];
    int boff  = (b > 0) ? sh[b - 1] : 0;
    __syncthreads();

    int j0 = b * CHUNK + 2 * t, j1 = j0 + 1;
    int v0 = (j0 < M) ? g_cnt[j0] : 0;
    int v1 = (j1 < M) ? g_cnt[j1] : 0;
    int ss = v0 + v1;
    sh[t] = ss; __syncthreads();
    for (int d = 1; d < 256; d <<= 1) {
        int u = (t >= d) ? sh[t - d] : 0;
        __syncthreads();
        sh[t] += u;
        __syncthreads();
    }
    int ex = boff + sh[t] - ss;
    if (j0 < M) {
        g_rowptr[j0] = ex; g_cursor[j0] = ex;
        g_invdeg[j0] = 1.0f / (float)(v0 + 1);
    }
    if (j1 < M) {
        g_rowptr[j1] = ex + v0; g_cursor[j1] = ex + v0;
        g_invdeg[j1] = 1.0f / (float)(v1 + 1);
    }
    if (b == 0 && t == 0) g_rowptr[M] = total;
}

// ---------------- fill: full grid ----------------
__global__ void fill_kernel(const int* __restrict__ ei, int E) {
    int e = blockIdx.x * blockDim.x + threadIdx.x;
    if (e >= E) return;
    int row, col;
    if (g_is64) {
        row = ei[2 * e];
        col = ei[2 * E + 2 * e];
    } else {
        row = ei[e];
        col = ei[E + e];
    }
    int pos = atomicAdd(&g_cursor[row], 1);
    g_adj[pos] = col;
}

// ---------------- SpMM: warp per row, gather-only (at L2 cap, proven) ----------------
__global__ void spmm_kernel(const float* __restrict__ src,
                            float* __restrict__ dst, int M) {
    int warp = (blockIdx.x * blockDim.x + threadIdx.x) >> 5;
    if (warp >= M) return;
    int lane = threadIdx.x & 31;

    const float4* s4 = (const float4*)src;
    size_t rowbase = (size_t)warp * (KDIM / 4);

    float4 a = s4[rowbase + lane];
    float ax = a.x, ay = a.y, az = a.z, aw = a.w;

    int e   = g_rowptr[warp];
    int end = g_rowptr[warp + 1];

    for (; e + 8 <= end; e += 8) {
        float4 v[8];
#pragma unroll
        for (int q = 0; q < 8; q++) {
            int j = g_adj[e + q];
            v[q] = s4[(size_t)j * (KDIM / 4) + lane];
        }
#pragma unroll
        for (int q = 0; q < 8; q++) {
            ax += v[q].x; ay += v[q].y; az += v[q].z; aw += v[q].w;
        }
    }
    for (; e < end; e++) {
        int j = g_adj[e];
        float4 v = s4[(size_t)j * (KDIM / 4) + lane];
        ax += v.x; ay += v.y; az += v.z; aw += v.w;
    }

    float inv = g_invdeg[warp];
    float4 o;
    o.x = ax * inv; o.y = ay * inv; o.z = az * inv; o.w = aw * inv;
    ((float4*)dst)[rowbase + lane] = o;
}

// ---------------- GEMM (R4-proven shape: TM=64, RPT=4, CT=16, 2 CTA/SM) ----------------
// h = relu(A[M,128] @ W[128,128] + bias).
// POST=false: dst = h (stride 128). POST=true: dst = h @ Wc[128,64] + bc (stride 64).
template <bool POST>
__global__ void __launch_bounds__(256, 2)
gemm_kernel(const float* __restrict__ A, const float* __restrict__ W,
            const float* __restrict__ bias,
            const float* __restrict__ Wc, const float* __restrict__ bc,
            float* __restrict__ dst, int M) {
    constexpr int K   = KDIM;
    constexpr int RPT = 4;
    constexpr int TM  = 64;

    extern __shared__ float sm[];
    float* Ws = sm;                  // 128*128 = 64KB
    float* As = sm + K * 128;        // 64*128  = 32KB

    int tid = threadIdx.x;
    int m0  = blockIdx.x * TM;

    for (int i = tid; i < K * 128 / 4; i += 256)
        ((float4*)Ws)[i] = ((const float4*)W)[i];
    for (int i = tid; i < TM * K / 4; i += 256) {
        int r  = i >> 5;
        int gr = m0 + r;
        ((float4*)As)[i] = (gr < M) ? ((const float4*)A)[(size_t)gr * 32 + (i & 31)]
                                    : make_float4(0.f, 0.f, 0.f, 0.f);
    }
    __syncthreads();

    int ct = tid % 16;
    int rt = tid / 16;               // 0..15
    int cL = ct * 4;
    int cH = 64 + ct * 4;

    u64 acc[RPT][4];
#pragma unroll
    for (int r = 0; r < RPT; r++)
#pragma unroll
        for (int p = 0; p < 4; p++) acc[r][p] = 0ull;

    const float* arow = As + (rt * RPT) * K;

#pragma unroll 2
    for (int k4 = 0; k4 < K / 4; k4++) {
        int kb = k4 * 4;
        float4 av[RPT];
#pragma unroll
        for (int r = 0; r < RPT; r++)
            av[r] = *(const float4*)&arow[r * K + kb];

#pragma unroll
        for (int kk = 0; kk < 4; kk++) {
            ulonglong2 wlo = *(const ulonglong2*)&Ws[(kb + kk) * 128 + cL];
            ulonglong2 whi = *(const ulonglong2*)&Ws[(kb + kk) * 128 + cH];
#pragma unroll
            for (int r = 0; r < RPT; r++) {
                float a = (kk == 0) ? av[r].x : (kk == 1) ? av[r].y
                        : (kk == 2) ? av[r].z : av[r].w;
                u64 aa = pack2(a, a);
                ffma2(acc[r][0], aa, wlo.x);
                ffma2(acc[r][1], aa, wlo.y);
                ffma2(acc[r][2], aa, whi.x);
                ffma2(acc[r][3], aa, whi.y);
            }
        }
    }

    float4 bvL = *(const float4*)&bias[cL];
    float4 bvH = *(const float4*)&bias[cH];

    if (!POST) {
#pragma unroll
        for (int r = 0; r < RPT; r++) {
            int gr = m0 + rt * RPT + r;
            if (gr >= M) continue;
            float o[8];
            unpack2(acc[r][0], o[0], o[1]);
            unpack2(acc[r][1], o[2], o[3]);
            unpack2(acc[r][2], o[4], o[5]);
            unpack2(acc[r][3], o[6], o[7]);
            o[0] += bvL.x; o[1] += bvL.y; o[2] += bvL.z; o[3] += bvL.w;
            o[4] += bvH.x; o[5] += bvH.y; o[6] += bvH.z; o[7] += bvH.w;
#pragma unroll
            for (int p = 0; p < 8; p++) o[p] = fmaxf(o[p], 0.f);
            *(float4*)&dst[(size_t)gr * 128 + cL] = make_float4(o[0], o[1], o[2], o[3]);
            *(float4*)&dst[(size_t)gr * 128 + cH] = make_float4(o[4], o[5], o[6], o[7]);
        }
        return;
    }

    // POST: h2 -> As, Wc -> Ws, GEMM2 -> dst (stride 64)
    __syncthreads();   // all GEMM1 reads of As/Ws done
#pragma unroll
    for (int r = 0; r < RPT; r++) {
        int lr = rt * RPT + r;
        float o[8];
        unpack2(acc[r][0], o[0], o[1]);
        unpack2(acc[r][1], o[2], o[3]);
        unpack2(acc[r][2], o[4], o[5]);
        unpack2(acc[r][3], o[6], o[7]);
        o[0] += bvL.x; o[1] += bvL.y; o[2] += bvL.z; o[3] += bvL.w;
        o[4] += bvH.x; o[5] += bvH.y; o[6] += bvH.z; o[7] += bvH.w;
#pragma unroll
        for (int p = 0; p < 8; p++) o[p] = fmaxf(o[p], 0.f);
        *(float4*)&As[lr * K + cL] = make_float4(o[0], o[1], o[2], o[3]);
        *(float4*)&As[lr * K + cH] = make_float4(o[4], o[5], o[6], o[7]);
    }
    for (int i = tid; i < K * OUTDIM / 4; i += 256)
        ((float4*)Ws)[i] = ((const float4*)Wc)[i];
    __syncthreads();

    // GEMM2: 64 rows x 64 cols. ct2=tid%16 (cols ct2*4), rt2=tid/16 (rows rt2*4..)
    int ct2 = tid % 16;
    int rt2 = tid / 16;
    int c2  = ct2 * 4;

    u64 acc2[4][2];
#pragma unroll
    for (int r = 0; r < 4; r++) { acc2[r][0] = 0ull; acc2[r][1] = 0ull; }

    const float* arow2 = As + (rt2 * 4) * K;

#pragma unroll 2
    for (int k4 = 0; k4 < K / 4; k4++) {
        int kb = k4 * 4;
        float4 av[4];
#pragma unroll
        for (int r = 0; r < 4; r++)
            av[r] = *(const float4*)&arow2[r * K + kb];
#pragma unroll
        for (int kk = 0; kk < 4; kk++) {
            ulonglong2 w = *(const ulonglong2*)&Ws[(kb + kk) * OUTDIM + c2];
#pragma unroll
            for (int r = 0; r < 4; r++) {
                float a = (kk == 0) ? av[r].x : (kk == 1) ? av[r].y
                        : (kk == 2) ? av[r].z : av[r].w;
                u64 aa = pack2(a, a);
                ffma2(acc2[r][0], aa, w.x);
                ffma2(acc2[r][1], aa, w.y);
            }
        }
    }

    float4 cv = *(const float4*)&bc[c2];
#pragma unroll
    for (int r = 0; r < 4; r++) {
        int gr = m0 + rt2 * 4 + r;
        if (gr >= M) continue;
        float o[4];
        unpack2(acc2[r][0], o[0], o[1]);
        unpack2(acc2[r][1], o[2], o[3]);
        o[0] += cv.x; o[1] += cv.y; o[2] += cv.z; o[3] += cv.w;
        *(float4*)&dst[(size_t)gr * OUTDIM + c2] = make_float4(o[0], o[1], o[2], o[3]);
    }
}

// ---------------- host launch ----------------
extern "C" void kernel_launch(void* const* d_in, const int* in_sizes, int n_in,
                              void* d_out, int out_size) {
    const float* x  = (const float*)d_in[0];
    const int*   ei = (const int*)d_in[1];
    const float* W1 = (const float*)d_in[2];
    const float* b1 = (const float*)d_in[3];
    const float* W2 = (const float*)d_in[4];
    const float* b2 = (const float*)d_in[5];
    const float* W3 = (const float*)d_in[6];
    const float* b3 = (const float*)d_in[7];
    const float* W4 = (const float*)d_in[8];
    const float* b4 = (const float*)d_in[9];
    float* out = (float*)d_out;

    int M = in_sizes[0] / KDIM;         // 50000
    int E = in_sizes[1] / 2;            // 800000
    int NB = (M + CHUNK - 1) / CHUNK;   // 98
    int ZB = (M + 255) / 256;           // zero blocks
    int WB = ((KDIM + 1) * OUTDIM + 255) / 256;  // wc blocks

    float *bufA, *bufB, *Wc, *bc;
    cudaGetSymbolAddress((void**)&bufA, g_bufA);
    cudaGetSymbolAddress((void**)&bufB, g_bufB);
    cudaGetSymbolAddress((void**)&Wc, g_Wc);
    cudaGetSymbolAddress((void**)&bc, g_bc);

    constexpr int SMEM = (KDIM * 128 + 64 * KDIM) * 4;   // 96KB
    cudaFuncSetAttribute(gemm_kernel<false>,
                         cudaFuncAttributeMaxDynamicSharedMemorySize, SMEM);
    cudaFuncSetAttribute(gemm_kernel<true>,
                         cudaFuncAttributeMaxDynamicSharedMemorySize, SMEM);

    // ---- CSR build ----
    initwc_kernel<<<ZB + WB, 256>>>(ei, M, ZB, W3, b3, W4, b4);
    count_kernel<<<(E + 511) / 512, 512>>>(ei, E);
    scan_kernel<<<NB, 256>>>(M, NB);
    fill_kernel<<<(E + 511) / 512, 512>>>(ei, E);

    int spmm_blocks = (M * 32 + 255) / 256;
    int gemm_blocks = (M + 63) / 64;

    // layer 1
    spmm_kernel<<<spmm_blocks, 256>>>(x, bufA, M);
    gemm_kernel<false><<<gemm_blocks, 256, SMEM>>>(bufA, W1, b1, nullptr, nullptr, bufB, M);

    // layer 2 + fused post_mp
    spmm_kernel<<<spmm_blocks, 256>>>(bufB, bufA, M);
    gemm_kernel<true><<<gemm_blocks, 256, SMEM>>>(bufA, W2, b2, Wc, bc, out, M);
}

// round 7
// speedup vs baseline: 1.4722x; 1.0214x over previous
#include <cuda_runtime.h>
#include <cstdint>

#define NN      50000
#define EE      800000
#define KDIM    128
#define OUTDIM  64

typedef unsigned long long u64;

// ---------------- device scratch ----------------
__device__ float g_bufA[NN * KDIM];
__device__ float g_bufB[NN * KDIM];
__device__ int   g_cnt[NN];
__device__ int   g_rowptr[NN + 1];
__device__ int   g_cursor[NN];
__device__ int   g_adj[EE];
__device__ float g_invdeg[NN];
__device__ float g_Wc[KDIM * OUTDIM];
__device__ float g_bc[OUTDIM];
__device__ int   g_is64;
__device__ int   g_bsum[256];
__device__ int   g_done;

// ---------------- packed fp32 helpers ----------------
__device__ __forceinline__ u64 pack2(float lo, float hi) {
    u64 r; asm("mov.b64 %0, {%1, %2};" : "=l"(r) : "f"(lo), "f"(hi)); return r;
}
__device__ __forceinline__ void unpack2(u64 v, float& lo, float& hi) {
    asm("mov.b64 {%0, %1}, %2;" : "=f"(lo), "=f"(hi) : "l"(v));
}
__device__ __forceinline__ void ffma2(u64& d, u64 a, u64 b) {
    asm("fma.rn.f32x2 %0, %1, %2, %3;" : "=l"(d) : "l"(a), "l"(b), "l"(d));
}

// ---------------- wc precompute (also resets g_done) ----------------
__global__ void wc_kernel(const float* __restrict__ W3, const float* __restrict__ b3,
                          const float* __restrict__ W4, const float* __restrict__ b4) {
    int blk = blockIdx.x;
    int c = threadIdx.x;
    if (blk == 0 && c == 0) g_done = 0;
    if (blk < KDIM) {
        float s = 0.0f;
        for (int m = 0; m < KDIM; m++)
            s += W3[blk * KDIM + m] * W4[m * OUTDIM + c];
        g_Wc[blk * OUTDIM + c] = s;
    } else {
        float s = b4[c];
        for (int m = 0; m < KDIM; m++)
            s += b3[m] * W4[m * OUTDIM + c];
        g_bc[c] = s;
    }
}

// ---------------- resident-grid spin barrier ----------------
__device__ __forceinline__ void gridbar(int target) {
    __syncthreads();
    if (threadIdx.x == 0) {
        __threadfence();
        atomicAdd(&g_done, 1);
        while (*(volatile int*)&g_done < target) { }
    }
    __syncthreads();
}

// ---------------- single persistent CSR build ----------------
// NB=148 blocks x 512 threads, all resident. Phases separated by grid barriers:
// zero+detect -> count -> chunk sums -> scan+emit -> fill.
__global__ void __launch_bounds__(512, 1)
csr_all_kernel(const int* __restrict__ ei, int E, int M, int NB) {
    __shared__ int sh[512];
    int b = blockIdx.x, t = threadIdx.x;
    int gstride = NB * 512;

    // phase 0: zero counters + dtype detect
    for (int i = b * 512 + t; i < M; i += gstride) g_cnt[i] = 0;
    if (b == 0 && t == 0) {
        int allz = 1;
        for (int e = 0; e < 64; e++) {
            if (ei[2 * e + 1] != 0) { allz = 0; break; }
        }
        g_is64 = allz;
    }
    gridbar(NB);
    int is64 = g_is64;

    // phase 1: count in-degrees
    for (int e = b * 512 + t; e < E; e += gstride) {
        int row = is64 ? ei[2 * e] : ei[e];
        atomicAdd(&g_cnt[row], 1);
    }
    gridbar(2 * NB);

    // phase 2: per-chunk sums (CH rows per block)
    int CH = (M + NB - 1) / NB;     // 338
    int lo = b * CH;
    int hi = lo + CH; if (hi > M) hi = M;
    {
        int s = 0;
        for (int i = lo + t; i < hi; i += 512) s += __ldcg(&g_cnt[i]);
        sh[t] = s; __syncthreads();
        for (int d = 256; d > 0; d >>= 1) {
            if (t < d) sh[t] += sh[t + d];
            __syncthreads();
        }
        if (t == 0) g_bsum[b] = sh[0];
    }
    gridbar(3 * NB);

    // phase 3: every block scans the NB chunk sums (NB <= 256)
    int boff, total;
    {
        int v = (t < NB) ? __ldcg(&g_bsum[t]) : 0;
        if (t < 256) sh[t] = v;
        __syncthreads();
        for (int d = 1; d < 256; d <<= 1) {
            int u = (t >= d && t < 256) ? sh[t - d] : 0;
            __syncthreads();
            if (t < 256) sh[t] += u;
            __syncthreads();
        }
        total = sh[NB - 1];
        boff  = (b > 0) ? sh[b - 1] : 0;
        __syncthreads();
    }

    // phase 3b: emit rowptr/cursor/invdeg (thread t handles row lo+t, t < CH <= 512)
    {
        int row = lo + t;
        int v = (t < CH && row < M) ? __ldcg(&g_cnt[row]) : 0;
        sh[t] = v; __syncthreads();
        for (int d = 1; d < 512; d <<= 1) {
            int u = (t >= d) ? sh[t - d] : 0;
            __syncthreads();
            sh[t] += u;
            __syncthreads();
        }
        int ex = boff + sh[t] - v;
        if (t < CH && row < M) {
            g_rowptr[row] = ex;
            g_cursor[row] = ex;
            g_invdeg[row] = 1.0f / (float)(v + 1);
        }
        if (b == 0 && t == 0) g_rowptr[M] = total;
    }
    gridbar(4 * NB);

    // phase 4: fill adjacency
    for (int e = b * 512 + t; e < E; e += gstride) {
        int row, col;
        if (is64) {
            row = ei[2 * e];
            col = ei[2 * E + 2 * e];
        } else {
            row = ei[e];
            col = ei[E + e];
        }
        int pos = atomicAdd(&g_cursor[row], 1);
        g_adj[pos] = col;
    }
}

// ---------------- SpMM: warp per row, gather-only (at L2 cap, proven) ----------------
__global__ void spmm_kernel(const float* __restrict__ src,
                            float* __restrict__ dst, int M) {
    int warp = (blockIdx.x * blockDim.x + threadIdx.x) >> 5;
    if (warp >= M) return;
    int lane = threadIdx.x & 31;

    const float4* s4 = (const float4*)src;
    size_t rowbase = (size_t)warp * (KDIM / 4);

    float4 a = s4[rowbase + lane];
    float ax = a.x, ay = a.y, az = a.z, aw = a.w;

    int e   = g_rowptr[warp];
    int end = g_rowptr[warp + 1];

    for (; e + 8 <= end; e += 8) {
        float4 v[8];
#pragma unroll
        for (int q = 0; q < 8; q++) {
            int j = g_adj[e + q];
            v[q] = s4[(size_t)j * (KDIM / 4) + lane];
        }
#pragma unroll
        for (int q = 0; q < 8; q++) {
            ax += v[q].x; ay += v[q].y; az += v[q].z; aw += v[q].w;
        }
    }
    for (; e < end; e++) {
        int j = g_adj[e];
        float4 v = s4[(size_t)j * (KDIM / 4) + lane];
        ax += v.x; ay += v.y; az += v.z; aw += v.w;
    }

    float inv = g_invdeg[warp];
    float4 o;
    o.x = ax * inv; o.y = ay * inv; o.z = az * inv; o.w = aw * inv;
    ((float4*)dst)[rowbase + lane] = o;
}

// ---------------- persistent pipelined GEMM ----------------
// grid=296 (2 CTA/SM). W staged once; tile loop with register prefetch of next As.
// h = relu(A[M,128]@W + bias); POST=false: dst=h (stride 128);
// POST=true: dst = h @ Wc[128,64] + bc (stride 64), Wc read via __ldg (L1-resident).
template <bool POST>
__global__ void __launch_bounds__(256, 2)
gemm_kernel(const float* __restrict__ A, const float* __restrict__ W,
            const float* __restrict__ bias,
            const float* __restrict__ Wc, const float* __restrict__ bc,
            float* __restrict__ dst, int M, int ntiles) {
    constexpr int K   = KDIM;
    constexpr int RPT = 4;

    extern __shared__ float sm[];
    float* Ws = sm;                  // 128*128 = 64KB
    float* As = sm + K * 128;        // 64*128  = 32KB

    int tid = threadIdx.x;

    // stage W once
    for (int i = tid; i < K * 128 / 4; i += 256)
        ((float4*)Ws)[i] = ((const float4*)W)[i];

    int ct = tid & 15;
    int rt = tid >> 4;
    int cL = ct * 4;
    int cH = 64 + ct * 4;

    float4 bvL = *(const float4*)&bias[cL];
    float4 bvH = *(const float4*)&bias[cH];

    const float4* A4 = (const float4*)A;
    float4 pf[8];

    // prefetch first tile
    {
        int m0 = blockIdx.x * 64;
#pragma unroll
        for (int j = 0; j < 8; j++) {
            int i = tid + j * 256;
            int gr = m0 + (i >> 5);
            pf[j] = (gr < M) ? A4[(size_t)gr * 32 + (i & 31)]
                             : make_float4(0.f, 0.f, 0.f, 0.f);
        }
    }
    __syncthreads();   // Ws staged

    for (int t = blockIdx.x; t < ntiles; t += gridDim.x) {
        int m0 = t * 64;

        // commit prefetched tile to smem
#pragma unroll
        for (int j = 0; j < 8; j++)
            ((float4*)As)[tid + j * 256] = pf[j];
        __syncthreads();

        // issue prefetch for next tile (overlaps with compute)
        int tn = t + gridDim.x;
        if (tn < ntiles) {
            int mn = tn * 64;
#pragma unroll
            for (int j = 0; j < 8; j++) {
                int i = tid + j * 256;
                int gr = mn + (i >> 5);
                pf[j] = (gr < M) ? A4[(size_t)gr * 32 + (i & 31)]
                                 : make_float4(0.f, 0.f, 0.f, 0.f);
            }
        }

        // GEMM1 mainloop (R4/R6-proven conflict-free FFMA2)
        u64 acc[RPT][4];
#pragma unroll
        for (int r = 0; r < RPT; r++)
#pragma unroll
            for (int p = 0; p < 4; p++) acc[r][p] = 0ull;

        const float* arow = As + (rt * RPT) * K;

#pragma unroll 2
        for (int k4 = 0; k4 < K / 4; k4++) {
            int kb = k4 * 4;
            float4 av[RPT];
#pragma unroll
            for (int r = 0; r < RPT; r++)
                av[r] = *(const float4*)&arow[r * K + kb];
#pragma unroll
            for (int kk = 0; kk < 4; kk++) {
                ulonglong2 wlo = *(const ulonglong2*)&Ws[(kb + kk) * 128 + cL];
                ulonglong2 whi = *(const ulonglong2*)&Ws[(kb + kk) * 128 + cH];
#pragma unroll
                for (int r = 0; r < RPT; r++) {
                    float a = (kk == 0) ? av[r].x : (kk == 1) ? av[r].y
                            : (kk == 2) ? av[r].z : av[r].w;
                    u64 aa = pack2(a, a);
                    ffma2(acc[r][0], aa, wlo.x);
                    ffma2(acc[r][1], aa, wlo.y);
                    ffma2(acc[r][2], aa, whi.x);
                    ffma2(acc[r][3], aa, whi.y);
                }
            }
        }

        if (!POST) {
#pragma unroll
            for (int r = 0; r < RPT; r++) {
                int gr = m0 + rt * RPT + r;
                if (gr >= M) continue;
                float o[8];
                unpack2(acc[r][0], o[0], o[1]);
                unpack2(acc[r][1], o[2], o[3]);
                unpack2(acc[r][2], o[4], o[5]);
                unpack2(acc[r][3], o[6], o[7]);
                o[0] += bvL.x; o[1] += bvL.y; o[2] += bvL.z; o[3] += bvL.w;
                o[4] += bvH.x; o[5] += bvH.y; o[6] += bvH.z; o[7] += bvH.w;
#pragma unroll
                for (int p = 0; p < 8; p++) o[p] = fmaxf(o[p], 0.f);
                *(float4*)&dst[(size_t)gr * 128 + cL] = make_float4(o[0], o[1], o[2], o[3]);
                *(float4*)&dst[(size_t)gr * 128 + cH] = make_float4(o[4], o[5], o[6], o[7]);
            }
            __syncthreads();   // As reads done before next tile's store
            continue;
        }

        // POST: h2 -> As, then GEMM2 with Wc via __ldg
        __syncthreads();       // GEMM1 As reads done
#pragma unroll
        for (int r = 0; r < RPT; r++) {
            int lr = rt * RPT + r;
            float o[8];
            unpack2(acc[r][0], o[0], o[1]);
            unpack2(acc[r][1], o[2], o[3]);
            unpack2(acc[r][2], o[4], o[5]);
            unpack2(acc[r][3], o[6], o[7]);
            o[0] += bvL.x; o[1] += bvL.y; o[2] += bvL.z; o[3] += bvL.w;
            o[4] += bvH.x; o[5] += bvH.y; o[6] += bvH.z; o[7] += bvH.w;
#pragma unroll
            for (int p = 0; p < 8; p++) o[p] = fmaxf(o[p], 0.f);
            *(float4*)&As[lr * K + cL] = make_float4(o[0], o[1], o[2], o[3]);
            *(float4*)&As[lr * K + cH] = make_float4(o[4], o[5], o[6], o[7]);
        }
        __syncthreads();       // h2 visible

        // GEMM2: 64x64, cols c2=ct*4, rows rt*4..
        int c2 = ct * 4;
        u64 acc2[4][2];
#pragma unroll
        for (int r = 0; r < 4; r++) { acc2[r][0] = 0ull; acc2[r][1] = 0ull; }

        const float* arow2 = As + (rt * 4) * K;

#pragma unroll 2
        for (int k4 = 0; k4 < K / 4; k4++) {
            int kb = k4 * 4;
            float4 av[4];
#pragma unroll
            for (int r = 0; r < 4; r++)
                av[r] = *(const float4*)&arow2[r * K + kb];
#pragma unroll
            for (int kk = 0; kk < 4; kk++) {
                ulonglong2 w = __ldg((const ulonglong2*)&Wc[(kb + kk) * OUTDIM + c2]);
#pragma unroll
                for (int r = 0; r < 4; r++) {
                    float a = (kk == 0) ? av[r].x : (kk == 1) ? av[r].y
                            : (kk == 2) ? av[r].z : av[r].w;
                    u64 aa = pack2(a, a);
                    ffma2(acc2[r][0], aa, w.x);
                    ffma2(acc2[r][1], aa, w.y);
                }
            }
        }

        float4 cv = *(const float4*)&bc[c2];
#pragma unroll
        for (int r = 0; r < 4; r++) {
            int gr = m0 + rt * 4 + r;
            if (gr >= M) continue;
            float o[4];
            unpack2(acc2[r][0], o[0], o[1]);
            unpack2(acc2[r][1], o[2], o[3]);
            o[0] += cv.x; o[1] += cv.y; o[2] += cv.z; o[3] += cv.w;
            *(float4*)&dst[(size_t)gr * OUTDIM + c2] = make_float4(o[0], o[1], o[2], o[3]);
        }
        __syncthreads();       // As reads done before next tile's store
    }
}

// ---------------- host launch ----------------
extern "C" void kernel_launch(void* const* d_in, const int* in_sizes, int n_in,
                              void* d_out, int out_size) {
    const float* x  = (const float*)d_in[0];
    const int*   ei = (const int*)d_in[1];
    const float* W1 = (const float*)d_in[2];
    const float* b1 = (const float*)d_in[3];
    const float* W2 = (const float*)d_in[4];
    const float* b2 = (const float*)d_in[5];
    const float* W3 = (const float*)d_in[6];
    const float* b3 = (const float*)d_in[7];
    const float* W4 = (const float*)d_in[8];
    const float* b4 = (const float*)d_in[9];
    float* out = (float*)d_out;

    int M = in_sizes[0] / KDIM;         // 50000
    int E = in_sizes[1] / 2;            // 800000
    int NB = 148;                       // resident CSR blocks

    float *bufA, *bufB, *Wc, *bc;
    cudaGetSymbolAddress((void**)&bufA, g_bufA);
    cudaGetSymbolAddress((void**)&bufB, g_bufB);
    cudaGetSymbolAddress((void**)&Wc, g_Wc);
    cudaGetSymbolAddress((void**)&bc, g_bc);

    constexpr int SMEM = (KDIM * 128 + 64 * KDIM) * 4;   // 96KB
    cudaFuncSetAttribute(gemm_kernel<false>,
                         cudaFuncAttributeMaxDynamicSharedMemorySize, SMEM);
    cudaFuncSetAttribute(gemm_kernel<true>,
                         cudaFuncAttributeMaxDynamicSharedMemorySize, SMEM);

    wc_kernel<<<KDIM + 1, OUTDIM>>>(W3, b3, W4, b4);
    csr_all_kernel<<<NB, 512>>>(ei, E, M, NB);

    int spmm_blocks = (M * 32 + 255) / 256;
    int ntiles = (M + 63) / 64;         // 782
    int ggrid = 296;                    // 2 CTAs/SM

    // layer 1
    spmm_kernel<<<spmm_blocks, 256>>>(x, bufA, M);
    gemm_kernel<false><<<ggrid, 256, SMEM>>>(bufA, W1, b1, nullptr, nullptr, bufB, M, ntiles);

    // layer 2 + fused post_mp
    spmm_kernel<<<spmm_blocks, 256>>>(bufB, bufA, M);
    gemm_kernel<true><<<ggrid, 256, SMEM>>>(bufA, W2, b2, Wc, bc, out, M, ntiles);
}